// round 1
// baseline (speedup 1.0000x reference)
#include <cuda_runtime.h>
#include <math.h>

#define BATCH 8
#define CIN 512
#define SEQT 2048
#define DF 512
#define NH 8
#define DH 64
#define MROWS (BATCH*SEQT)   // 16384

// Scratch (allocation-free rule: __device__ globals)
__device__ float g_hn [MROWS * DF];
__device__ float g_q  [MROWS * DF];
__device__ float g_k  [MROWS * DF];
__device__ float g_v  [MROWS * DF];
__device__ float g_ctx[MROWS * DF];
__device__ float g_y  [MROWS * DF];

// ---------------------------------------------------------------------------
// LayerNorm over channel dim: x (B, C, T) -> hn (B*T, C)
// ---------------------------------------------------------------------------
__global__ void ln_kernel(const float* __restrict__ x, const float* __restrict__ gamma,
                          const float* __restrict__ beta, float* __restrict__ hn) {
    int m = blockIdx.x;
    int b = m >> 11;        // / SEQT
    int t = m & (SEQT - 1);
    const float* xb = x + (size_t)b * CIN * SEQT + t;
    int tid = threadIdx.x;  // 128
    float vals[4];
    float s = 0.f, s2 = 0.f;
#pragma unroll
    for (int i = 0; i < 4; i++) {
        int c = tid + i * 128;
        float v = xb[(size_t)c * SEQT];
        vals[i] = v; s += v; s2 += v * v;
    }
#pragma unroll
    for (int off = 16; off; off >>= 1) {
        s  += __shfl_xor_sync(0xffffffffu, s,  off);
        s2 += __shfl_xor_sync(0xffffffffu, s2, off);
    }
    __shared__ float sm[4], sm2[4];
    int wid = tid >> 5;
    if ((tid & 31) == 0) { sm[wid] = s; sm2[wid] = s2; }
    __syncthreads();
    s  = sm[0]  + sm[1]  + sm[2]  + sm[3];
    s2 = sm2[0] + sm2[1] + sm2[2] + sm2[3];
    float mean = s * (1.f / CIN);
    float var  = s2 * (1.f / CIN) - mean * mean;
    float rstd = rsqrtf(var + 1e-5f);
    float* o = hn + (size_t)m * CIN;
#pragma unroll
    for (int i = 0; i < 4; i++) {
        int c = tid + i * 128;
        o[c] = (vals[i] - mean) * rstd * gamma[c] + beta[c];
    }
}

// ---------------------------------------------------------------------------
// C[M,N] = A[M,K] * W[K,N] + bias[N]    (all row-major, fp32)
// 128x128 block tile, BK=16, 256 threads, 8x8 per thread
// ---------------------------------------------------------------------------
__global__ __launch_bounds__(256, 2)
void gemm_kernel(const float* __restrict__ A, const float* __restrict__ W,
                 const float* __restrict__ bias, float* __restrict__ C,
                 int M, int N, int K) {
    __shared__ float As[16][128];   // [k][m]
    __shared__ float Ws[16][128];   // [k][n]
    int tid = threadIdx.x;
    int bm = blockIdx.y * 128;
    int bn = blockIdx.x * 128;
    int tm = (tid >> 4) << 3;
    int tn = (tid & 15) << 3;
    float acc[8][8];
#pragma unroll
    for (int i = 0; i < 8; i++)
#pragma unroll
        for (int j = 0; j < 8; j++) acc[i][j] = 0.f;

    for (int k0 = 0; k0 < K; k0 += 16) {
#pragma unroll
        for (int l = 0; l < 2; l++) {
            int f = tid + l * 256;          // 512 float4 per tile
            int r  = f >> 2, c4 = (f & 3) << 2;   // A: 4 float4 per row
            float4 av = *(const float4*)(A + (size_t)(bm + r) * K + k0 + c4);
            As[c4 + 0][r] = av.x; As[c4 + 1][r] = av.y;
            As[c4 + 2][r] = av.z; As[c4 + 3][r] = av.w;
            int rw = f >> 5, cw = (f & 31) << 2;  // W: 32 float4 per row
            *(float4*)(&Ws[rw][cw]) = *(const float4*)(W + (size_t)(k0 + rw) * N + bn + cw);
        }
        __syncthreads();
#pragma unroll
        for (int kk = 0; kk < 16; kk++) {
            float4 a0 = *(const float4*)(&As[kk][tm]);
            float4 a1 = *(const float4*)(&As[kk][tm + 4]);
            float4 b0 = *(const float4*)(&Ws[kk][tn]);
            float4 b1 = *(const float4*)(&Ws[kk][tn + 4]);
            float a[8] = {a0.x, a0.y, a0.z, a0.w, a1.x, a1.y, a1.z, a1.w};
            float bb[8] = {b0.x, b0.y, b0.z, b0.w, b1.x, b1.y, b1.z, b1.w};
#pragma unroll
            for (int i = 0; i < 8; i++)
#pragma unroll
                for (int j = 0; j < 8; j++)
                    acc[i][j] += a[i] * bb[j];
        }
        __syncthreads();
    }
#pragma unroll
    for (int i = 0; i < 8; i++) {
#pragma unroll
        for (int j = 0; j < 8; j += 4) {
            float4 o;
            o.x = acc[i][j + 0] + bias[bn + tn + j + 0];
            o.y = acc[i][j + 1] + bias[bn + tn + j + 1];
            o.z = acc[i][j + 2] + bias[bn + tn + j + 2];
            o.w = acc[i][j + 3] + bias[bn + tn + j + 3];
            *(float4*)(C + (size_t)(bm + tm + i) * N + bn + tn + j) = o;
        }
    }
}

// ---------------------------------------------------------------------------
// Flash attention, causal, fp32. 64 queries x 64 keys per tile, dh=64.
// q,k,v,ctx layout: (B, T, H*dh) row-major. 256 threads = 16x16, 4x4 microtile.
// ---------------------------------------------------------------------------
#define SP 72   // smem row stride (floats), multiple of 8 for float4 alignment

__global__ __launch_bounds__(256, 2)
void flash_kernel(const float* __restrict__ q, const float* __restrict__ k,
                  const float* __restrict__ v, float* __restrict__ ctx) {
    extern __shared__ float smf[];
    float* Qs = smf;              // [d][r]
    float* Ks = Qs + 64 * SP;     // [d][c]
    float* Vs = Ks + 64 * SP;     // [c][e]
    float* Ps = Vs + 64 * SP;     // [c][r]
    int qt = blockIdx.x, bh = blockIdx.y;
    int b = bh >> 3, h = bh & 7;
    int tid = threadIdx.x;
    int tx = tid & 15, ty = tid >> 4;

    const float* qbp = q + (size_t)(b * SEQT + qt * 64) * DF + h * DH;
#pragma unroll
    for (int l = 0; l < 4; l++) {
        int f = tid + l * 256;            // 1024 float4 = 64 rows x 16
        int r = f >> 4, d4 = (f & 15) << 2;
        float4 vv = *(const float4*)(qbp + (size_t)r * DF + d4);
        Qs[(d4 + 0) * SP + r] = vv.x;
        Qs[(d4 + 1) * SP + r] = vv.y;
        Qs[(d4 + 2) * SP + r] = vv.z;
        Qs[(d4 + 3) * SP + r] = vv.w;
    }
    float m_i[4], l_i[4], acc[4][4];
#pragma unroll
    for (int i = 0; i < 4; i++) {
        m_i[i] = -1e30f; l_i[i] = 0.f;
#pragma unroll
        for (int j = 0; j < 4; j++) acc[i][j] = 0.f;
    }

    for (int kt = 0; kt <= qt; kt++) {
        __syncthreads();   // prior iteration's reads of Ks/Vs/Ps complete
        const float* kbp = k + (size_t)(b * SEQT + kt * 64) * DF + h * DH;
        const float* vbp = v + (size_t)(b * SEQT + kt * 64) * DF + h * DH;
#pragma unroll
        for (int l = 0; l < 4; l++) {
            int f = tid + l * 256;
            int r = f >> 4, d4 = (f & 15) << 2;
            float4 kv = *(const float4*)(kbp + (size_t)r * DF + d4);
            Ks[(d4 + 0) * SP + r] = kv.x;
            Ks[(d4 + 1) * SP + r] = kv.y;
            Ks[(d4 + 2) * SP + r] = kv.z;
            Ks[(d4 + 3) * SP + r] = kv.w;
            float4 vv = *(const float4*)(vbp + (size_t)r * DF + d4);
            *(float4*)(Vs + r * SP + d4) = vv;
        }
        __syncthreads();

        // S = Q K^T
        float s4[4][4];
#pragma unroll
        for (int i = 0; i < 4; i++)
#pragma unroll
            for (int j = 0; j < 4; j++) s4[i][j] = 0.f;
#pragma unroll
        for (int d = 0; d < 64; d++) {
            float4 aq = *(const float4*)(Qs + d * SP + ty * 4);
            float4 ak = *(const float4*)(Ks + d * SP + tx * 4);
            float a[4]  = {aq.x, aq.y, aq.z, aq.w};
            float bb[4] = {ak.x, ak.y, ak.z, ak.w};
#pragma unroll
            for (int i = 0; i < 4; i++)
#pragma unroll
                for (int j = 0; j < 4; j++)
                    s4[i][j] += a[i] * bb[j];
        }
        const float scale = 0.125f;   // 1/sqrt(64)
        if (kt == qt) {
#pragma unroll
            for (int i = 0; i < 4; i++)
#pragma unroll
                for (int j = 0; j < 4; j++) {
                    s4[i][j] *= scale;
                    if (tx * 4 + j > ty * 4 + i) s4[i][j] = -1e30f;
                }
        } else {
#pragma unroll
            for (int i = 0; i < 4; i++)
#pragma unroll
                for (int j = 0; j < 4; j++) s4[i][j] *= scale;
        }

        // online softmax (rows spread across the 16 tx-threads in a half warp)
#pragma unroll
        for (int i = 0; i < 4; i++) {
            float rm = fmaxf(fmaxf(s4[i][0], s4[i][1]), fmaxf(s4[i][2], s4[i][3]));
#pragma unroll
            for (int off = 8; off; off >>= 1)
                rm = fmaxf(rm, __shfl_xor_sync(0xffffffffu, rm, off));
            float mn = fmaxf(m_i[i], rm);
            float alpha = __expf(m_i[i] - mn);
            m_i[i] = mn;
            float rs = 0.f;
#pragma unroll
            for (int j = 0; j < 4; j++) {
                float p = __expf(s4[i][j] - mn);
                s4[i][j] = p;
                rs += p;
            }
#pragma unroll
            for (int off = 8; off; off >>= 1)
                rs += __shfl_xor_sync(0xffffffffu, rs, off);
            l_i[i] = l_i[i] * alpha + rs;
#pragma unroll
            for (int j = 0; j < 4; j++) acc[i][j] *= alpha;
        }

        // stage P transposed [c][r]
#pragma unroll
        for (int i = 0; i < 4; i++)
#pragma unroll
            for (int j = 0; j < 4; j++)
                Ps[(tx * 4 + j) * SP + ty * 4 + i] = s4[i][j];
        __syncthreads();

        // O += P V
#pragma unroll
        for (int c = 0; c < 64; c++) {
            float4 ap = *(const float4*)(Ps + c * SP + ty * 4);
            float4 av = *(const float4*)(Vs + c * SP + tx * 4);
            float a[4]  = {ap.x, ap.y, ap.z, ap.w};
            float bb[4] = {av.x, av.y, av.z, av.w};
#pragma unroll
            for (int i = 0; i < 4; i++)
#pragma unroll
                for (int j = 0; j < 4; j++)
                    acc[i][j] += a[i] * bb[j];
        }
    }

#pragma unroll
    for (int i = 0; i < 4; i++) {
        float inv = 1.f / l_i[i];
        float4 o;
        o.x = acc[i][0] * inv;
        o.y = acc[i][1] * inv;
        o.z = acc[i][2] * inv;
        o.w = acc[i][3] * inv;
        *(float4*)(ctx + (size_t)(b * SEQT + qt * 64 + ty * 4 + i) * DF + h * DH + tx * 4) = o;
    }
}

// ---------------------------------------------------------------------------
// out[b][c][t] = x[b][c][t] + y[b][t][c]   (transpose + residual)
// ---------------------------------------------------------------------------
__global__ void trans_add_kernel(const float* __restrict__ x, const float* __restrict__ y,
                                 float* __restrict__ out) {
    __shared__ float tile[32][33];
    int b = blockIdx.z;
    int t0 = blockIdx.x * 32, c0 = blockIdx.y * 32;
#pragma unroll
    for (int i = 0; i < 4; i++) {
        int t = t0 + threadIdx.y + i * 8;
        tile[threadIdx.y + i * 8][threadIdx.x] =
            y[((size_t)b * SEQT + t) * CIN + c0 + threadIdx.x];
    }
    __syncthreads();
#pragma unroll
    for (int i = 0; i < 4; i++) {
        int c = c0 + threadIdx.y + i * 8;
        size_t idx = ((size_t)b * CIN + c) * SEQT + t0 + threadIdx.x;
        out[idx] = x[idx] + tile[threadIdx.x][threadIdx.y + i * 8];
    }
}

// ---------------------------------------------------------------------------
extern "C" void kernel_launch(void* const* d_in, const int* in_sizes, int n_in,
                              void* d_out, int out_size) {
    const float* x     = (const float*)d_in[0];
    const float* gamma = (const float*)d_in[1];
    const float* beta  = (const float*)d_in[2];
    const float* wq = (const float*)d_in[3];
    const float* bq = (const float*)d_in[4];
    const float* wk = (const float*)d_in[5];
    const float* bk = (const float*)d_in[6];
    const float* wv = (const float*)d_in[7];
    const float* bv = (const float*)d_in[8];
    const float* wo = (const float*)d_in[9];
    const float* bo = (const float*)d_in[10];
    float* out = (float*)d_out;

    float *hn, *qb, *kb, *vb, *cb, *yb;
    cudaGetSymbolAddress((void**)&hn, g_hn);
    cudaGetSymbolAddress((void**)&qb, g_q);
    cudaGetSymbolAddress((void**)&kb, g_k);
    cudaGetSymbolAddress((void**)&vb, g_v);
    cudaGetSymbolAddress((void**)&cb, g_ctx);
    cudaGetSymbolAddress((void**)&yb, g_y);

    ln_kernel<<<MROWS, 128>>>(x, gamma, beta, hn);

    dim3 gg(DF / 128, MROWS / 128);   // (4, 128)
    gemm_kernel<<<gg, 256>>>(hn, wq, bq, qb, MROWS, DF, CIN);
    gemm_kernel<<<gg, 256>>>(hn, wk, bk, kb, MROWS, DF, CIN);
    gemm_kernel<<<gg, 256>>>(hn, wv, bv, vb, MROWS, DF, CIN);

    size_t smem = (size_t)4 * 64 * SP * sizeof(float);   // 73728 B
    cudaFuncSetAttribute(flash_kernel, cudaFuncAttributeMaxDynamicSharedMemorySize, (int)smem);
    flash_kernel<<<dim3(SEQT / 64, BATCH * NH), 256, smem>>>(qb, kb, vb, cb);

    gemm_kernel<<<gg, 256>>>(cb, wo, bo, yb, MROWS, CIN, DF);

    trans_add_kernel<<<dim3(SEQT / 32, CIN / 32, BATCH), dim3(32, 8)>>>(x, yb, out);
}

// round 3
// speedup vs baseline: 2.8807x; 2.8807x over previous
#include <cuda_runtime.h>
#include <cstdint>
#include <math.h>

#define BATCH 8
#define CIN 512
#define SEQT 2048
#define DF 512
#define NH 8
#define DH 64
#define MROWS (BATCH*SEQT)   // 16384

// Scratch (allocation-free rule: __device__ globals)
__device__ float g_hn [MROWS * DF];
__device__ float g_q  [MROWS * DF];
__device__ float g_k  [MROWS * DF];
__device__ float g_v  [MROWS * DF];
__device__ float g_ctx[MROWS * DF];
__device__ float g_y  [MROWS * DF];
__device__ float g_wt [4 * CIN * DF];   // tf32-rounded weights

// ===========================================================================
// helpers
// ===========================================================================
__device__ __forceinline__ uint32_t tfu(float x) {
    uint32_t u;
    asm("cvt.rna.tf32.f32 %0, %1;" : "=r"(u) : "f"(x));
    return u;
}
__device__ __forceinline__ float tfr(float x) { return __uint_as_float(tfu(x)); }
__device__ __forceinline__ float ex2(float x) {
    float y;
    asm("ex2.approx.f32 %0, %1;" : "=f"(y) : "f"(x));
    return y;
}
__device__ __forceinline__ void mma8(float* d, const uint32_t* a, const uint32_t* b) {
    asm volatile(
        "mma.sync.aligned.m16n8k8.row.col.f32.tf32.tf32.f32 "
        "{%0,%1,%2,%3}, {%4,%5,%6,%7}, {%8,%9}, {%0,%1,%2,%3};"
        : "+f"(d[0]), "+f"(d[1]), "+f"(d[2]), "+f"(d[3])
        : "r"(a[0]), "r"(a[1]), "r"(a[2]), "r"(a[3]), "r"(b[0]), "r"(b[1]));
}
__device__ __forceinline__ void cp16(uint32_t saddr, const void* g) {
    asm volatile("cp.async.cg.shared.global [%0], [%1], 16;" :: "r"(saddr), "l"(g));
}
#define CP_COMMIT() asm volatile("cp.async.commit_group;" ::: "memory")
#define CP_WAIT1()  asm volatile("cp.async.wait_group 1;" ::: "memory")
#define CP_WAIT0()  asm volatile("cp.async.wait_group 0;" ::: "memory")
__device__ __forceinline__ uint32_t smem_u32(const void* p) {
    uint32_t a;
    asm("{ .reg .u64 t; cvta.to.shared.u64 t, %1; cvt.u32.u64 %0, t; }" : "=r"(a) : "l"(p));
    return a;
}

// ===========================================================================
// LayerNorm: x (B, C, T) -> hn (B*T, C), output rounded to tf32
// ===========================================================================
__global__ void ln_kernel(const float* __restrict__ x, const float* __restrict__ gamma,
                          const float* __restrict__ beta, float* __restrict__ hn) {
    int m = blockIdx.x;
    int b = m >> 11;
    int t = m & (SEQT - 1);
    const float* xb = x + (size_t)b * CIN * SEQT + t;
    int tid = threadIdx.x;  // 128
    float vals[4];
    float s = 0.f, s2 = 0.f;
#pragma unroll
    for (int i = 0; i < 4; i++) {
        int c = tid + i * 128;
        float v = xb[(size_t)c * SEQT];
        vals[i] = v; s += v; s2 += v * v;
    }
#pragma unroll
    for (int off = 16; off; off >>= 1) {
        s  += __shfl_xor_sync(0xffffffffu, s,  off);
        s2 += __shfl_xor_sync(0xffffffffu, s2, off);
    }
    __shared__ float sm[4], sm2[4];
    int wid = tid >> 5;
    if ((tid & 31) == 0) { sm[wid] = s; sm2[wid] = s2; }
    __syncthreads();
    s  = sm[0]  + sm[1]  + sm[2]  + sm[3];
    s2 = sm2[0] + sm2[1] + sm2[2] + sm2[3];
    float mean = s * (1.f / CIN);
    float var  = s2 * (1.f / CIN) - mean * mean;
    float rstd = rsqrtf(var + 1e-5f);
    float* o = hn + (size_t)m * CIN;
#pragma unroll
    for (int i = 0; i < 4; i++) {
        int c = tid + i * 128;
        o[c] = tfr((vals[i] - mean) * rstd * gamma[c] + beta[c]);
    }
}

// ===========================================================================
// elementwise tf32 rounding (weights, once)
// ===========================================================================
__global__ void cvt_kernel(const float* __restrict__ a, float* __restrict__ o) {
    int i = blockIdx.x * 256 + threadIdx.x;
    o[i] = tfr(a[i]);
}

// ===========================================================================
// mma.sync tf32 GEMM: C[M,512] = A[M,512] @ W[512,512] + bias, optional
// scale and tf32-rounding of output. 128x128 tile, BK=32, 256 thr (8 warps 4x2)
// smem: double-buffered A[128][36], B(W)[32][132]  (strides ≡ 4 mod 32)
// ===========================================================================
#define AS_ST 36
#define BS_ST 132
#define A_TILE_F (128 * AS_ST)              // 4608 floats
#define B_TILE_F (32 * BS_ST)               // 4224 floats
#define BUF_F    (A_TILE_F + B_TILE_F)      // 8832 floats
#define GEMM_SMEM (2 * BUF_F * 4)           // 70656 bytes

__global__ __launch_bounds__(256, 2)
void gemm_mma(const float* __restrict__ A, const float* __restrict__ W,
              const float* __restrict__ bias, float* __restrict__ C,
              float scale, int rnd) {
    extern __shared__ float smf[];
    uint32_t sb = smem_u32(smf);
    const int tid = threadIdx.x;
    const int wid = tid >> 5, lane = tid & 31;
    const int g = lane >> 2, tg = lane & 3;
    const int bm = blockIdx.y * 128, bn = blockIdx.x * 128;
    const int wm = (wid & 3) * 32, wn = (wid >> 2) * 64;

    // cp.async issue helper (inlined twice)
    const int ar = tid >> 3, ac = (tid & 7) << 2;     // A: row, col4
    const int br = tid >> 5, bc = (tid & 31) << 2;    // B: row, col4
#define GEMM_ISSUE(kt, buf) do {                                                   \
        uint32_t as_ = sb + (uint32_t)(buf) * (BUF_F * 4);                         \
        uint32_t bs_ = as_ + A_TILE_F * 4;                                         \
        const float* Ag = A + (size_t)(bm + ar) * 512 + (kt) * 32 + ac;            \
        _Pragma("unroll")                                                          \
        for (int i_ = 0; i_ < 4; i_++)                                             \
            cp16(as_ + (uint32_t)(((ar + i_ * 32) * AS_ST + ac) * 4),              \
                 Ag + (size_t)i_ * 32 * 512);                                      \
        const float* Wg = W + (size_t)((kt) * 32 + br) * 512 + bn + bc;            \
        _Pragma("unroll")                                                          \
        for (int i_ = 0; i_ < 4; i_++)                                             \
            cp16(bs_ + (uint32_t)(((br + i_ * 8) * BS_ST + bc) * 4),               \
                 Wg + (size_t)i_ * 8 * 512);                                       \
        CP_COMMIT();                                                               \
    } while (0)

    float acc[2][8][4];
#pragma unroll
    for (int mt = 0; mt < 2; mt++)
#pragma unroll
        for (int nt = 0; nt < 8; nt++)
#pragma unroll
            for (int j = 0; j < 4; j++) acc[mt][nt][j] = 0.f;

    GEMM_ISSUE(0, 0);

    for (int kt = 0; kt < 16; kt++) {
        if (kt < 15) { GEMM_ISSUE(kt + 1, (kt + 1) & 1); CP_WAIT1(); }
        else CP_WAIT0();
        __syncthreads();
        const float* As = smf + (kt & 1) * BUF_F;
        const float* Bs = As + A_TILE_F;
#pragma unroll
        for (int ks = 0; ks < 4; ks++) {
            const int k0 = ks * 8;
            uint32_t a[2][4], b[8][2];
#pragma unroll
            for (int mt = 0; mt < 2; mt++) {
                const float* ap = As + (wm + mt * 16 + g) * AS_ST + k0 + tg;
                a[mt][0] = __float_as_uint(ap[0]);
                a[mt][1] = __float_as_uint(ap[8 * AS_ST]);
                a[mt][2] = __float_as_uint(ap[4]);
                a[mt][3] = __float_as_uint(ap[8 * AS_ST + 4]);
            }
#pragma unroll
            for (int nt = 0; nt < 8; nt++) {
                const float* bp = Bs + (k0 + tg) * BS_ST + wn + nt * 8 + g;
                b[nt][0] = __float_as_uint(bp[0]);
                b[nt][1] = __float_as_uint(bp[4 * BS_ST]);
            }
#pragma unroll
            for (int mt = 0; mt < 2; mt++)
#pragma unroll
                for (int nt = 0; nt < 8; nt++)
                    mma8(acc[mt][nt], a[mt], b[nt]);
        }
        __syncthreads();
    }

#pragma unroll
    for (int mt = 0; mt < 2; mt++) {
        int row = bm + wm + mt * 16 + g;
#pragma unroll
        for (int nt = 0; nt < 8; nt++) {
            int col = bn + wn + nt * 8 + 2 * tg;
            float b0 = bias[col], b1 = bias[col + 1];
            float o0 = (acc[mt][nt][0] + b0) * scale;
            float o1 = (acc[mt][nt][1] + b1) * scale;
            float o2 = (acc[mt][nt][2] + b0) * scale;
            float o3 = (acc[mt][nt][3] + b1) * scale;
            if (rnd) { o0 = tfr(o0); o1 = tfr(o1); o2 = tfr(o2); o3 = tfr(o3); }
            float2 v0 = {o0, o1}, v1 = {o2, o3};
            *(float2*)(C + (size_t)row * 512 + col) = v0;
            *(float2*)(C + (size_t)(row + 8) * 512 + col) = v1;
        }
    }
}

// ===========================================================================
// Flash attention, causal, tf32 mma.sync. CTA = 128 q-rows, 8 warps x 16 rows.
// q prescaled by log2e/8 (in its GEMM epilogue); softmax in exp2 domain.
// smem: Qs[128][68], Ks[64][68], Vs[64][68], Ps[128][68]  (stride ≡ 4 mod 32)
// ===========================================================================
#define FST 68
#define FLASH_SMEM (384 * FST * 4)   // 104448 bytes

__global__ __launch_bounds__(256, 2)
void flash_mma(const float* __restrict__ q, const float* __restrict__ k,
               const float* __restrict__ v, float* __restrict__ ctx) {
    extern __shared__ float fs[];
    float* Qs = fs;
    float* Ks = Qs + 128 * FST;
    float* Vs = Ks + 64 * FST;
    float* Ps = Vs + 64 * FST;
    const int qt = blockIdx.x, bh = blockIdx.y;
    const int b = bh >> 3, h = bh & 7;
    const int qb = qt * 128;
    const int tid = threadIdx.x, wid = tid >> 5, lane = tid & 31;
    const int g = lane >> 2, tg = lane & 3;
    const int rowbase = qb + wid * 16;

    // load Q block (already tf32-rounded & prescaled)
    const float* qp = q + (size_t)(b * SEQT + qb) * 512 + h * 64;
#pragma unroll
    for (int i = 0; i < 8; i++) {
        int f = tid + i * 256;
        int r = f >> 4, c = (f & 15) << 2;
        *(float4*)(Qs + r * FST + c) = *(const float4*)(qp + (size_t)r * 512 + c);
    }

    float o[8][4];
#pragma unroll
    for (int nt = 0; nt < 8; nt++)
#pragma unroll
        for (int j = 0; j < 4; j++) o[nt][j] = 0.f;
    float m0 = -1e29f, m1 = -1e29f, l0 = 0.f, l1 = 0.f;

    const int ktmax = 2 * qt + 2;
    for (int kt = 0; kt < ktmax; kt++) {
        __syncthreads();
        const float* kp = k + (size_t)(b * SEQT + kt * 64) * 512 + h * 64;
        const float* vp = v + (size_t)(b * SEQT + kt * 64) * 512 + h * 64;
#pragma unroll
        for (int i = 0; i < 4; i++) {
            int f = tid + i * 256;
            int r = f >> 4, c = (f & 15) << 2;
            *(float4*)(Ks + r * FST + c) = *(const float4*)(kp + (size_t)r * 512 + c);
            *(float4*)(Vs + r * FST + c) = *(const float4*)(vp + (size_t)r * 512 + c);
        }
        __syncthreads();

        if (kt * 64 <= rowbase + 15) {   // warp strip has at least one valid key
            float S[8][4];
#pragma unroll
            for (int nt = 0; nt < 8; nt++)
#pragma unroll
                for (int j = 0; j < 4; j++) S[nt][j] = 0.f;

            // S = Q K^T
#pragma unroll
            for (int ks = 0; ks < 8; ks++) {
                uint32_t a[4];
                const float* ap = Qs + (wid * 16 + g) * FST + ks * 8 + tg;
                a[0] = __float_as_uint(ap[0]);
                a[1] = __float_as_uint(ap[8 * FST]);
                a[2] = __float_as_uint(ap[4]);
                a[3] = __float_as_uint(ap[8 * FST + 4]);
#pragma unroll
                for (int nt = 0; nt < 8; nt++) {
                    uint32_t bfr[2];
                    const float* bp = Ks + (nt * 8 + g) * FST + ks * 8 + tg;
                    bfr[0] = __float_as_uint(bp[0]);
                    bfr[1] = __float_as_uint(bp[4]);
                    mma8(S[nt], a, bfr);
                }
            }

            // causal mask on diagonal tiles
            if (kt * 64 + 63 > rowbase) {
#pragma unroll
                for (int nt = 0; nt < 8; nt++)
#pragma unroll
                    for (int j = 0; j < 4; j++) {
                        int col = kt * 64 + nt * 8 + 2 * tg + (j & 1);
                        int row = rowbase + g + ((j >> 1) << 3);
                        if (col > row) S[nt][j] = -1e30f;
                    }
            }

            // online softmax (rows g and g+8; cols spread over quad lanes)
            float rm0 = -1e30f, rm1 = -1e30f;
#pragma unroll
            for (int nt = 0; nt < 8; nt++) {
                rm0 = fmaxf(rm0, fmaxf(S[nt][0], S[nt][1]));
                rm1 = fmaxf(rm1, fmaxf(S[nt][2], S[nt][3]));
            }
            rm0 = fmaxf(rm0, __shfl_xor_sync(0xffffffffu, rm0, 1));
            rm0 = fmaxf(rm0, __shfl_xor_sync(0xffffffffu, rm0, 2));
            rm1 = fmaxf(rm1, __shfl_xor_sync(0xffffffffu, rm1, 1));
            rm1 = fmaxf(rm1, __shfl_xor_sync(0xffffffffu, rm1, 2));
            float mn0 = fmaxf(m0, rm0), mn1 = fmaxf(m1, rm1);
            float al0 = ex2(m0 - mn0), al1 = ex2(m1 - mn1);
            m0 = mn0; m1 = mn1;
            float rs0 = 0.f, rs1 = 0.f;
#pragma unroll
            for (int nt = 0; nt < 8; nt++) {
                S[nt][0] = ex2(S[nt][0] - mn0); rs0 += S[nt][0];
                S[nt][1] = ex2(S[nt][1] - mn0); rs0 += S[nt][1];
                S[nt][2] = ex2(S[nt][2] - mn1); rs1 += S[nt][2];
                S[nt][3] = ex2(S[nt][3] - mn1); rs1 += S[nt][3];
            }
            rs0 += __shfl_xor_sync(0xffffffffu, rs0, 1);
            rs0 += __shfl_xor_sync(0xffffffffu, rs0, 2);
            rs1 += __shfl_xor_sync(0xffffffffu, rs1, 1);
            rs1 += __shfl_xor_sync(0xffffffffu, rs1, 2);
            l0 = l0 * al0 + rs0;
            l1 = l1 * al1 + rs1;
#pragma unroll
            for (int nt = 0; nt < 8; nt++) {
                o[nt][0] *= al0; o[nt][1] *= al0;
                o[nt][2] *= al1; o[nt][3] *= al1;
            }

            // stage P (tf32) into per-warp-private smem
#pragma unroll
            for (int nt = 0; nt < 8; nt++) {
                uint2 p01 = {tfu(S[nt][0]), tfu(S[nt][1])};
                uint2 p23 = {tfu(S[nt][2]), tfu(S[nt][3])};
                *(uint2*)(Ps + (wid * 16 + g) * FST + nt * 8 + 2 * tg) = p01;
                *(uint2*)(Ps + (wid * 16 + 8 + g) * FST + nt * 8 + 2 * tg) = p23;
            }
            __syncwarp();

            // O += P V
#pragma unroll
            for (int ks = 0; ks < 8; ks++) {
                uint32_t a[4];
                const float* ap = Ps + (wid * 16 + g) * FST + ks * 8 + tg;
                a[0] = __float_as_uint(ap[0]);
                a[1] = __float_as_uint(ap[8 * FST]);
                a[2] = __float_as_uint(ap[4]);
                a[3] = __float_as_uint(ap[8 * FST + 4]);
#pragma unroll
                for (int nt = 0; nt < 8; nt++) {
                    uint32_t bfr[2];
                    const float* bp = Vs + (ks * 8 + tg) * FST + nt * 8 + g;
                    bfr[0] = __float_as_uint(bp[0]);
                    bfr[1] = __float_as_uint(bp[4 * FST]);
                    mma8(o[nt], a, bfr);
                }
            }
        }
    }

    // epilogue: normalize, round to tf32 (feeds o-proj mma), write
    float inv0 = 1.f / l0, inv1 = 1.f / l1;
    float* cp0 = ctx + (size_t)(b * SEQT + rowbase + g) * 512 + h * 64;
    float* cp1 = cp0 + (size_t)8 * 512;
#pragma unroll
    for (int nt = 0; nt < 8; nt++) {
        int col = nt * 8 + 2 * tg;
        float2 v0 = {tfr(o[nt][0] * inv0), tfr(o[nt][1] * inv0)};
        float2 v1 = {tfr(o[nt][2] * inv1), tfr(o[nt][3] * inv1)};
        *(float2*)(cp0 + col) = v0;
        *(float2*)(cp1 + col) = v1;
    }
}

// ===========================================================================
// out[b][c][t] = x[b][c][t] + y[b][t][c]
// ===========================================================================
__global__ void trans_add_kernel(const float* __restrict__ x, const float* __restrict__ y,
                                 float* __restrict__ out) {
    __shared__ float tile[32][33];
    int b = blockIdx.z;
    int t0 = blockIdx.x * 32, c0 = blockIdx.y * 32;
#pragma unroll
    for (int i = 0; i < 4; i++) {
        int t = t0 + threadIdx.y + i * 8;
        tile[threadIdx.y + i * 8][threadIdx.x] =
            y[((size_t)b * SEQT + t) * CIN + c0 + threadIdx.x];
    }
    __syncthreads();
#pragma unroll
    for (int i = 0; i < 4; i++) {
        int c = c0 + threadIdx.y + i * 8;
        size_t idx = ((size_t)b * CIN + c) * SEQT + t0 + threadIdx.x;
        out[idx] = x[idx] + tile[threadIdx.x][threadIdx.y + i * 8];
    }
}

// ===========================================================================
extern "C" void kernel_launch(void* const* d_in, const int* in_sizes, int n_in,
                              void* d_out, int out_size) {
    const float* x     = (const float*)d_in[0];
    const float* gamma = (const float*)d_in[1];
    const float* beta  = (const float*)d_in[2];
    const float* wq = (const float*)d_in[3];
    const float* bq = (const float*)d_in[4];
    const float* wk = (const float*)d_in[5];
    const float* bk = (const float*)d_in[6];
    const float* wv = (const float*)d_in[7];
    const float* bv = (const float*)d_in[8];
    const float* wo = (const float*)d_in[9];
    const float* bo = (const float*)d_in[10];
    float* out = (float*)d_out;

    float *hn, *qb, *kb, *vb, *cb, *yb, *wt;
    cudaGetSymbolAddress((void**)&hn, g_hn);
    cudaGetSymbolAddress((void**)&qb, g_q);
    cudaGetSymbolAddress((void**)&kb, g_k);
    cudaGetSymbolAddress((void**)&vb, g_v);
    cudaGetSymbolAddress((void**)&cb, g_ctx);
    cudaGetSymbolAddress((void**)&yb, g_y);
    cudaGetSymbolAddress((void**)&wt, g_wt);
    float* wtq = wt;
    float* wtk = wt + CIN * DF;
    float* wtv = wt + 2 * CIN * DF;
    float* wto = wt + 3 * CIN * DF;

    ln_kernel<<<MROWS, 128>>>(x, gamma, beta, hn);

    cvt_kernel<<<CIN * DF / 256, 256>>>(wq, wtq);
    cvt_kernel<<<CIN * DF / 256, 256>>>(wk, wtk);
    cvt_kernel<<<CIN * DF / 256, 256>>>(wv, wtv);
    cvt_kernel<<<CIN * DF / 256, 256>>>(wo, wto);

    cudaFuncSetAttribute(gemm_mma, cudaFuncAttributeMaxDynamicSharedMemorySize, GEMM_SMEM);
    dim3 gg(DF / 128, MROWS / 128);   // (4, 128)
    const float qscale = 0.125f * 1.44269504088896f;   // fold 1/sqrt(dh) * log2(e) into Q
    gemm_mma<<<gg, 256, GEMM_SMEM>>>(hn, wtq, bq, qb, qscale, 1);
    gemm_mma<<<gg, 256, GEMM_SMEM>>>(hn, wtk, bk, kb, 1.0f, 1);
    gemm_mma<<<gg, 256, GEMM_SMEM>>>(hn, wtv, bv, vb, 1.0f, 1);

    cudaFuncSetAttribute(flash_mma, cudaFuncAttributeMaxDynamicSharedMemorySize, FLASH_SMEM);
    flash_mma<<<dim3(SEQT / 128, BATCH * NH), 256, FLASH_SMEM>>>(qb, kb, vb, cb);

    gemm_mma<<<gg, 256, GEMM_SMEM>>>(cb, wto, bo, yb, 1.0f, 0);

    trans_add_kernel<<<dim3(SEQT / 32, CIN / 32, BATCH), dim3(32, 8)>>>(x, yb, out);
}

// round 4
// speedup vs baseline: 7.4335x; 2.5805x over previous
#include <cuda_runtime.h>
#include <cuda_bf16.h>
#include <cstdint>
#include <math.h>

#define BATCH 8
#define CIN 512
#define SEQT 2048
#define DF 512
#define NH 8
#define DH 64
#define MROWS (BATCH*SEQT)   // 16384

// Scratch (allocation-free rule: __device__ globals)
__device__ __nv_bfloat16 g_hn [MROWS * DF];
__device__ __nv_bfloat16 g_q  [MROWS * DF];
__device__ __nv_bfloat16 g_k  [MROWS * DF];
__device__ __nv_bfloat16 g_v  [MROWS * DF];
__device__ __nv_bfloat16 g_ctx[MROWS * DF];
__device__ float         g_y  [MROWS * DF];
__device__ __nv_bfloat16 g_wtb[4 * CIN * DF];   // bf16 weights

// ===========================================================================
// helpers
// ===========================================================================
__device__ __forceinline__ uint32_t pk(float lo, float hi) {
    uint32_t d;
    asm("cvt.rn.bf16x2.f32 %0, %1, %2;" : "=r"(d) : "f"(hi), "f"(lo));
    return d;
}
__device__ __forceinline__ float ex2(float x) {
    float y;
    asm("ex2.approx.f32 %0, %1;" : "=f"(y) : "f"(x));
    return y;
}
__device__ __forceinline__ void mma16(float* d, const uint32_t* a, const uint32_t* b) {
    asm volatile(
        "mma.sync.aligned.m16n8k16.row.col.f32.bf16.bf16.f32 "
        "{%0,%1,%2,%3}, {%4,%5,%6,%7}, {%8,%9}, {%0,%1,%2,%3};"
        : "+f"(d[0]), "+f"(d[1]), "+f"(d[2]), "+f"(d[3])
        : "r"(a[0]), "r"(a[1]), "r"(a[2]), "r"(a[3]), "r"(b[0]), "r"(b[1]));
}
__device__ __forceinline__ void ldsm4(uint32_t* r, uint32_t a) {
    asm volatile("ldmatrix.sync.aligned.m8n8.x4.shared.b16 {%0,%1,%2,%3}, [%4];"
        : "=r"(r[0]), "=r"(r[1]), "=r"(r[2]), "=r"(r[3]) : "r"(a));
}
__device__ __forceinline__ void ldsm4t(uint32_t* r, uint32_t a) {
    asm volatile("ldmatrix.sync.aligned.m8n8.x4.trans.shared.b16 {%0,%1,%2,%3}, [%4];"
        : "=r"(r[0]), "=r"(r[1]), "=r"(r[2]), "=r"(r[3]) : "r"(a));
}
__device__ __forceinline__ void cp16(uint32_t saddr, const void* g) {
    asm volatile("cp.async.cg.shared.global [%0], [%1], 16;" :: "r"(saddr), "l"(g));
}
#define CP_COMMIT() asm volatile("cp.async.commit_group;" ::: "memory")
#define CP_WAIT1()  asm volatile("cp.async.wait_group 1;" ::: "memory")
#define CP_WAIT0()  asm volatile("cp.async.wait_group 0;" ::: "memory")
__device__ __forceinline__ uint32_t smem_u32(const void* p) {
    uint32_t a;
    asm("{ .reg .u64 t; cvta.to.shared.u64 t, %1; cvt.u32.u64 %0, t; }" : "=r"(a) : "l"(p));
    return a;
}

// ===========================================================================
// LayerNorm: x (B, C, T) -> hn (B*T, C) bf16.  Coalesced two-pass tiles.
// grid (T/32, B), 256 threads (tx = t-lane, cy = c-lane)
// ===========================================================================
__global__ void ln_kernel(const float* __restrict__ x, const float* __restrict__ gamma,
                          const float* __restrict__ beta, __nv_bfloat16* __restrict__ hn) {
    int b = blockIdx.y, t0 = blockIdx.x * 32;
    int tid = threadIdx.x;
    int tx = tid & 31, cy = tid >> 5;   // 8 c-lanes
    const float* xp = x + (size_t)b * CIN * SEQT + t0;
    float s = 0.f, s2 = 0.f;
#pragma unroll 8
    for (int c = cy; c < CIN; c += 8) {
        float v = xp[(size_t)c * SEQT + tx];
        s += v; s2 += v * v;
    }
    __shared__ float ss[8][32], ss2[8][32], mean_s[32], rstd_s[32];
    ss[cy][tx] = s; ss2[cy][tx] = s2;
    __syncthreads();
    if (cy == 0) {
        float S = 0.f, S2 = 0.f;
#pragma unroll
        for (int i = 0; i < 8; i++) { S += ss[i][tx]; S2 += ss2[i][tx]; }
        float mean = S * (1.f / CIN);
        float var = S2 * (1.f / CIN) - mean * mean;
        mean_s[tx] = mean;
        rstd_s[tx] = rsqrtf(var + 1e-5f);
    }
    __syncthreads();
    float mean = mean_s[tx], rstd = rstd_s[tx];
    __shared__ float tile[32][33];
    for (int c0 = 0; c0 < CIN; c0 += 32) {
#pragma unroll
        for (int j = 0; j < 4; j++) {
            int c = c0 + cy + j * 8;
            tile[cy + j * 8][tx] = (xp[(size_t)c * SEQT + tx] - mean) * rstd * gamma[c] + beta[c];
        }
        __syncthreads();
#pragma unroll
        for (int j = 0; j < 4; j++) {
            int t = cy + j * 8;
            hn[(size_t)(b * SEQT + t0 + t) * CIN + c0 + tx] = __float2bfloat16(tile[tx][t]);
        }
        __syncthreads();
    }
}

// ===========================================================================
// weights fp32 -> bf16
// ===========================================================================
__global__ void cvt_kernel(const float* __restrict__ a, __nv_bfloat16* __restrict__ o) {
    int i = (blockIdx.x * 256 + threadIdx.x) * 4;
    float4 v = *(const float4*)(a + i);
    uint2 p = {pk(v.x, v.y), pk(v.z, v.w)};
    *(uint2*)((char*)o + (size_t)i * 2) = p;
}

// ===========================================================================
// bf16 GEMM: C[M,512] = A[M,512] @ W[512,512] + bias (fp32 accum)
// 128x128 tile, BK=64, 256 thr (8 warps 4m x 2n), cp.async double-buffered,
// ldmatrix fragments, XOR-swizzled smem.
// A smem: [128 rows][64 bf16] = 128 B/row (8 chunks), chunk' = c ^ (r&7)
// B smem: [64 k][128 n] = 256 B/row (16 chunks), chunk' = c ^ (r&7)
// ===========================================================================
#define GA_SZ 16384
#define GB_SZ 16384
#define GBUF  (GA_SZ + GB_SZ)
#define GEMM_SMEM (2 * GBUF)   // 65536

template<int OUTF32>
__global__ __launch_bounds__(256, 2)
void gemm_bf16(const __nv_bfloat16* __restrict__ A, const __nv_bfloat16* __restrict__ W,
               const float* __restrict__ bias, void* __restrict__ Cv, float scale) {
    extern __shared__ char sm[];
    uint32_t sb = smem_u32(sm);
    const int tid = threadIdx.x;
    const int wid = tid >> 5, lane = tid & 31;
    const int g = lane >> 2, tg = lane & 3;
    const int bm = blockIdx.y * 128, bn = blockIdx.x * 128;
    const int wm = (wid & 3) * 32, wn = (wid >> 2) * 64;

#define G_ISSUE(kt, buf) do {                                                        \
        uint32_t base_ = sb + (uint32_t)(buf) * GBUF;                                \
        _Pragma("unroll")                                                            \
        for (int i_ = 0; i_ < 4; i_++) {                                             \
            int idx = tid + i_ * 256;                                                \
            int r = idx >> 3, c = idx & 7;                                           \
            cp16(base_ + r * 128 + ((c ^ (r & 7)) << 4),                             \
                 A + (size_t)(bm + r) * 512 + (kt) * 64 + c * 8);                    \
        }                                                                            \
        _Pragma("unroll")                                                            \
        for (int i_ = 0; i_ < 4; i_++) {                                             \
            int idx = tid + i_ * 256;                                                \
            int r = idx >> 4, c = idx & 15;                                          \
            cp16(base_ + GA_SZ + r * 256 + ((c ^ (r & 7)) << 4),                     \
                 W + (size_t)((kt) * 64 + r) * 512 + bn + c * 8);                    \
        }                                                                            \
        CP_COMMIT();                                                                 \
    } while (0)

    float acc[2][8][4];
#pragma unroll
    for (int mt = 0; mt < 2; mt++)
#pragma unroll
        for (int nt = 0; nt < 8; nt++)
#pragma unroll
            for (int j = 0; j < 4; j++) acc[mt][nt][j] = 0.f;

    G_ISSUE(0, 0);
    for (int kt = 0; kt < 8; kt++) {
        if (kt < 7) { G_ISSUE(kt + 1, (kt + 1) & 1); CP_WAIT1(); }
        else CP_WAIT0();
        __syncthreads();
        uint32_t base = sb + (kt & 1) * GBUF;
#pragma unroll
        for (int ks = 0; ks < 4; ks++) {
            uint32_t a[2][4];
#pragma unroll
            for (int mt = 0; mt < 2; mt++) {
                int row = wm + mt * 16 + (lane & 7) + ((lane & 8) ? 8 : 0);
                int c = ks * 2 + ((lane >> 4) & 1);
                ldsm4(a[mt], base + row * 128 + ((c ^ (row & 7)) << 4));
            }
            uint32_t bb[4][4];
#pragma unroll
            for (int j = 0; j < 4; j++) {
                int krow = ks * 16 + (lane & 7) + ((lane & 8) ? 8 : 0);
                int c = ((wn + j * 16) >> 3) + ((lane >> 4) & 1);
                ldsm4t(bb[j], base + GA_SZ + krow * 256 + ((c ^ (krow & 7)) << 4));
            }
#pragma unroll
            for (int mt = 0; mt < 2; mt++)
#pragma unroll
                for (int j = 0; j < 4; j++) {
                    mma16(acc[mt][2 * j], a[mt], &bb[j][0]);
                    mma16(acc[mt][2 * j + 1], a[mt], &bb[j][2]);
                }
        }
        __syncthreads();
    }

#pragma unroll
    for (int mt = 0; mt < 2; mt++) {
        int row = bm + wm + mt * 16 + g;
#pragma unroll
        for (int nt = 0; nt < 8; nt++) {
            int col = bn + wn + nt * 8 + 2 * tg;
            float b0 = bias[col], b1 = bias[col + 1];
            float o0 = (acc[mt][nt][0] + b0) * scale;
            float o1 = (acc[mt][nt][1] + b1) * scale;
            float o2 = (acc[mt][nt][2] + b0) * scale;
            float o3 = (acc[mt][nt][3] + b1) * scale;
            if (OUTF32) {
                float* C = (float*)Cv;
                float2 v0 = {o0, o1}, v1 = {o2, o3};
                *(float2*)(C + (size_t)row * 512 + col) = v0;
                *(float2*)(C + (size_t)(row + 8) * 512 + col) = v1;
            } else {
                uint32_t* C = (uint32_t*)Cv;
                C[((size_t)row * 512 + col) >> 1] = pk(o0, o1);
                C[((size_t)(row + 8) * 512 + col) >> 1] = pk(o2, o3);
            }
        }
    }
#undef G_ISSUE
}

// ===========================================================================
// Flash attention, causal, bf16 mma. CTA = 128 q rows, 8 warps x 16 rows.
// Q prescaled by log2e/8 in its projection; softmax in exp2 domain.
// P converted to bf16 A-fragments in registers (no smem staging).
// smem: Qs 16KB + 2 x (K 8KB + V 8KB) = 48KB, XOR swizzle, cp.async 2-stage.
// ===========================================================================
#define FQ_SZ 16384
#define FKV_SZ 16384
#define FLASH_SMEM (FQ_SZ + 2 * FKV_SZ)   // 49152

__global__ __launch_bounds__(256, 2)
void flash_bf16(const __nv_bfloat16* __restrict__ q, const __nv_bfloat16* __restrict__ k,
                const __nv_bfloat16* __restrict__ v, __nv_bfloat16* __restrict__ ctx) {
    extern __shared__ char sm[];
    uint32_t sb = smem_u32(sm);
    const int qt = blockIdx.x, bh = blockIdx.y;
    const int b = bh >> 3, h = bh & 7;
    const int qb = qt * 128;
    const int tid = threadIdx.x, wid = tid >> 5, lane = tid & 31;
    const int g = lane >> 2, tg = lane & 3;
    const int rowbase = qb + wid * 16;
    const int ktmax = 2 * qt + 2;

    const __nv_bfloat16* qp = q + (size_t)(b * SEQT + qb) * 512 + h * 64;
    const __nv_bfloat16* kb0 = k + (size_t)b * SEQT * 512 + h * 64;
    const __nv_bfloat16* vb0 = v + (size_t)b * SEQT * 512 + h * 64;

#define F_ISSUE(kt, buf) do {                                                        \
        uint32_t base_ = sb + FQ_SZ + (uint32_t)(buf) * FKV_SZ;                      \
        const __nv_bfloat16* kp_ = kb0 + (size_t)(kt) * 64 * 512;                    \
        const __nv_bfloat16* vp_ = vb0 + (size_t)(kt) * 64 * 512;                    \
        _Pragma("unroll")                                                            \
        for (int i_ = 0; i_ < 2; i_++) {                                             \
            int idx = tid + i_ * 256;                                                \
            int r = idx >> 3, c = idx & 7;                                           \
            uint32_t off = r * 128 + ((c ^ (r & 7)) << 4);                           \
            cp16(base_ + off, kp_ + (size_t)r * 512 + c * 8);                        \
            cp16(base_ + 8192 + off, vp_ + (size_t)r * 512 + c * 8);                 \
        }                                                                            \
        CP_COMMIT();                                                                 \
    } while (0)

    // group 0: Q + KV(0)
#pragma unroll
    for (int i = 0; i < 4; i++) {
        int idx = tid + i * 256;
        int r = idx >> 3, c = idx & 7;
        cp16(sb + r * 128 + ((c ^ (r & 7)) << 4), qp + (size_t)r * 512 + c * 8);
    }
    {
        uint32_t base_ = sb + FQ_SZ;
#pragma unroll
        for (int i = 0; i < 2; i++) {
            int idx = tid + i * 256;
            int r = idx >> 3, c = idx & 7;
            uint32_t off = r * 128 + ((c ^ (r & 7)) << 4);
            cp16(base_ + off, kb0 + (size_t)r * 512 + c * 8);
            cp16(base_ + 8192 + off, vb0 + (size_t)r * 512 + c * 8);
        }
        CP_COMMIT();
    }
    if (ktmax > 1) F_ISSUE(1, 1);

    float o[8][4];
#pragma unroll
    for (int nt = 0; nt < 8; nt++)
#pragma unroll
        for (int j = 0; j < 4; j++) o[nt][j] = 0.f;
    float m0 = -1e29f, m1 = -1e29f, l0 = 0.f, l1 = 0.f;
    uint32_t aq[4][4];

    for (int kt = 0; kt < ktmax; kt++) {
        if (kt + 1 < ktmax) CP_WAIT1(); else CP_WAIT0();
        __syncthreads();
        if (kt == 0) {
#pragma unroll
            for (int ks = 0; ks < 4; ks++) {
                int row = wid * 16 + (lane & 7) + ((lane & 8) ? 8 : 0);
                int c = ks * 2 + ((lane >> 4) & 1);
                ldsm4(aq[ks], sb + row * 128 + ((c ^ (row & 7)) << 4));
            }
        }
        if (kt * 64 <= rowbase + 15) {
            uint32_t base = sb + FQ_SZ + (kt & 1) * FKV_SZ;
            float S[8][4];
#pragma unroll
            for (int nt = 0; nt < 8; nt++)
#pragma unroll
                for (int j = 0; j < 4; j++) S[nt][j] = 0.f;

            // S = Q K^T
#pragma unroll
            for (int ks = 0; ks < 4; ks++) {
#pragma unroll
                for (int j = 0; j < 4; j++) {
                    uint32_t kbf[4];
                    int krow = j * 16 + (lane & 7) + ((lane & 16) ? 8 : 0);
                    int c = ks * 2 + ((lane >> 3) & 1);
                    ldsm4(kbf, base + krow * 128 + ((c ^ (krow & 7)) << 4));
                    mma16(S[2 * j], aq[ks], &kbf[0]);
                    mma16(S[2 * j + 1], aq[ks], &kbf[2]);
                }
            }

            // causal mask (diagonal tiles only)
            if (kt * 64 + 63 > rowbase) {
#pragma unroll
                for (int nt = 0; nt < 8; nt++)
#pragma unroll
                    for (int j = 0; j < 4; j++) {
                        int col = kt * 64 + nt * 8 + 2 * tg + (j & 1);
                        int row = rowbase + g + ((j >> 1) << 3);
                        if (col > row) S[nt][j] = -1e30f;
                    }
            }

            // online softmax (rows g and g+8)
            float rm0 = -1e30f, rm1 = -1e30f;
#pragma unroll
            for (int nt = 0; nt < 8; nt++) {
                rm0 = fmaxf(rm0, fmaxf(S[nt][0], S[nt][1]));
                rm1 = fmaxf(rm1, fmaxf(S[nt][2], S[nt][3]));
            }
            rm0 = fmaxf(rm0, __shfl_xor_sync(0xffffffffu, rm0, 1));
            rm0 = fmaxf(rm0, __shfl_xor_sync(0xffffffffu, rm0, 2));
            rm1 = fmaxf(rm1, __shfl_xor_sync(0xffffffffu, rm1, 1));
            rm1 = fmaxf(rm1, __shfl_xor_sync(0xffffffffu, rm1, 2));
            float mn0 = fmaxf(m0, rm0), mn1 = fmaxf(m1, rm1);
            float al0 = ex2(m0 - mn0), al1 = ex2(m1 - mn1);
            m0 = mn0; m1 = mn1;
            float rs0 = 0.f, rs1 = 0.f;
#pragma unroll
            for (int nt = 0; nt < 8; nt++) {
                S[nt][0] = ex2(S[nt][0] - mn0); rs0 += S[nt][0];
                S[nt][1] = ex2(S[nt][1] - mn0); rs0 += S[nt][1];
                S[nt][2] = ex2(S[nt][2] - mn1); rs1 += S[nt][2];
                S[nt][3] = ex2(S[nt][3] - mn1); rs1 += S[nt][3];
            }
            rs0 += __shfl_xor_sync(0xffffffffu, rs0, 1);
            rs0 += __shfl_xor_sync(0xffffffffu, rs0, 2);
            rs1 += __shfl_xor_sync(0xffffffffu, rs1, 1);
            rs1 += __shfl_xor_sync(0xffffffffu, rs1, 2);
            l0 = l0 * al0 + rs0;
            l1 = l1 * al1 + rs1;
#pragma unroll
            for (int nt = 0; nt < 8; nt++) {
                o[nt][0] *= al0; o[nt][1] *= al0;
                o[nt][2] *= al1; o[nt][3] *= al1;
            }

            // O += P V  (P packed straight from S accumulators)
#pragma unroll
            for (int ksp = 0; ksp < 4; ksp++) {
                uint32_t ap[4] = {
                    pk(S[2 * ksp][0], S[2 * ksp][1]),
                    pk(S[2 * ksp][2], S[2 * ksp][3]),
                    pk(S[2 * ksp + 1][0], S[2 * ksp + 1][1]),
                    pk(S[2 * ksp + 1][2], S[2 * ksp + 1][3])};
#pragma unroll
                for (int j = 0; j < 4; j++) {
                    uint32_t vbf[4];
                    int krow = ksp * 16 + (lane & 7) + ((lane & 8) ? 8 : 0);
                    int c = j * 2 + ((lane >> 4) & 1);
                    ldsm4t(vbf, base + 8192 + krow * 128 + ((c ^ (krow & 7)) << 4));
                    mma16(o[2 * j], ap, &vbf[0]);
                    mma16(o[2 * j + 1], ap, &vbf[2]);
                }
            }
        }
        __syncthreads();
        if (kt + 2 < ktmax) F_ISSUE(kt + 2, kt & 1);
    }

    float inv0 = 1.f / l0, inv1 = 1.f / l1;
    uint32_t* c0p = (uint32_t*)(ctx + (size_t)(b * SEQT + rowbase + g) * 512 + h * 64);
    uint32_t* c1p = (uint32_t*)(ctx + (size_t)(b * SEQT + rowbase + g + 8) * 512 + h * 64);
#pragma unroll
    for (int nt = 0; nt < 8; nt++) {
        int cw = (nt * 8 + 2 * tg) >> 1;
        c0p[cw] = pk(o[nt][0] * inv0, o[nt][1] * inv0);
        c1p[cw] = pk(o[nt][2] * inv1, o[nt][3] * inv1);
    }
#undef F_ISSUE
}

// ===========================================================================
// out[b][c][t] = x[b][c][t] + y[b][t][c]
// ===========================================================================
__global__ void trans_add_kernel(const float* __restrict__ x, const float* __restrict__ y,
                                 float* __restrict__ out) {
    __shared__ float tile[32][33];
    int b = blockIdx.z;
    int t0 = blockIdx.x * 32, c0 = blockIdx.y * 32;
#pragma unroll
    for (int i = 0; i < 4; i++) {
        int t = t0 + threadIdx.y + i * 8;
        tile[threadIdx.y + i * 8][threadIdx.x] =
            y[((size_t)b * SEQT + t) * CIN + c0 + threadIdx.x];
    }
    __syncthreads();
#pragma unroll
    for (int i = 0; i < 4; i++) {
        int c = c0 + threadIdx.y + i * 8;
        size_t idx = ((size_t)b * CIN + c) * SEQT + t0 + threadIdx.x;
        out[idx] = x[idx] + tile[threadIdx.x][threadIdx.y + i * 8];
    }
}

// ===========================================================================
extern "C" void kernel_launch(void* const* d_in, const int* in_sizes, int n_in,
                              void* d_out, int out_size) {
    const float* x     = (const float*)d_in[0];
    const float* gamma = (const float*)d_in[1];
    const float* beta  = (const float*)d_in[2];
    const float* wq = (const float*)d_in[3];
    const float* bq = (const float*)d_in[4];
    const float* wk = (const float*)d_in[5];
    const float* bk = (const float*)d_in[6];
    const float* wv = (const float*)d_in[7];
    const float* bv = (const float*)d_in[8];
    const float* wo = (const float*)d_in[9];
    const float* bo = (const float*)d_in[10];
    float* out = (float*)d_out;

    __nv_bfloat16 *hn, *qb2, *kb2, *vb2, *cb, *wtb;
    float *yb;
    cudaGetSymbolAddress((void**)&hn,  g_hn);
    cudaGetSymbolAddress((void**)&qb2, g_q);
    cudaGetSymbolAddress((void**)&kb2, g_k);
    cudaGetSymbolAddress((void**)&vb2, g_v);
    cudaGetSymbolAddress((void**)&cb,  g_ctx);
    cudaGetSymbolAddress((void**)&yb,  g_y);
    cudaGetSymbolAddress((void**)&wtb, g_wtb);
    __nv_bfloat16* wtq = wtb;
    __nv_bfloat16* wtk = wtb + CIN * DF;
    __nv_bfloat16* wtv = wtb + 2 * CIN * DF;
    __nv_bfloat16* wto = wtb + 3 * CIN * DF;

    ln_kernel<<<dim3(SEQT / 32, BATCH), 256>>>(x, gamma, beta, hn);

    cvt_kernel<<<CIN * DF / 1024, 256>>>(wq, wtq);
    cvt_kernel<<<CIN * DF / 1024, 256>>>(wk, wtk);
    cvt_kernel<<<CIN * DF / 1024, 256>>>(wv, wtv);
    cvt_kernel<<<CIN * DF / 1024, 256>>>(wo, wto);

    cudaFuncSetAttribute(gemm_bf16<0>, cudaFuncAttributeMaxDynamicSharedMemorySize, GEMM_SMEM);
    cudaFuncSetAttribute(gemm_bf16<1>, cudaFuncAttributeMaxDynamicSharedMemorySize, GEMM_SMEM);
    dim3 gg(DF / 128, MROWS / 128);   // (4, 128)
    const float qscale = 0.125f * 1.44269504088896f;   // 1/sqrt(dh) * log2(e)
    gemm_bf16<0><<<gg, 256, GEMM_SMEM>>>(hn, wtq, bq, qb2, qscale);
    gemm_bf16<0><<<gg, 256, GEMM_SMEM>>>(hn, wtk, bk, kb2, 1.0f);
    gemm_bf16<0><<<gg, 256, GEMM_SMEM>>>(hn, wtv, bv, vb2, 1.0f);

    cudaFuncSetAttribute(flash_bf16, cudaFuncAttributeMaxDynamicSharedMemorySize, FLASH_SMEM);
    flash_bf16<<<dim3(SEQT / 128, BATCH * NH), 256, FLASH_SMEM>>>(qb2, kb2, vb2, cb);

    gemm_bf16<1><<<gg, 256, GEMM_SMEM>>>(cb, wto, bo, yb, 1.0f);

    trans_add_kernel<<<dim3(SEQT / 32, CIN / 32, BATCH), dim3(32, 8)>>>(x, yb, out);
}

// round 5
// speedup vs baseline: 7.9476x; 1.0692x over previous
#include <cuda_runtime.h>
#include <cuda_bf16.h>
#include <cstdint>
#include <math.h>

#define BATCH 8
#define CIN 512
#define SEQT 2048
#define DF 512
#define NH 8
#define DH 64
#define MROWS (BATCH*SEQT)   // 16384

// Scratch (allocation-free rule: __device__ globals)
__device__ __nv_bfloat16 g_hn  [MROWS * DF];          // LN output
__device__ __nv_bfloat16 g_qkv [MROWS * 3 * DF];      // fused q|k|v, row stride 1536
__device__ __nv_bfloat16 g_ctx [MROWS * DF];
__device__ __nv_bfloat16 g_wqkv[CIN * 3 * DF];        // packed bf16 weights [512][1536]
__device__ __nv_bfloat16 g_wo  [CIN * DF];
__device__ float         g_bqkv[3 * DF];

// ===========================================================================
// helpers
// ===========================================================================
__device__ __forceinline__ uint32_t pk(float lo, float hi) {
    uint32_t d;
    asm("cvt.rn.bf16x2.f32 %0, %1, %2;" : "=r"(d) : "f"(hi), "f"(lo));
    return d;
}
__device__ __forceinline__ float ex2(float x) {
    float y;
    asm("ex2.approx.f32 %0, %1;" : "=f"(y) : "f"(x));
    return y;
}
__device__ __forceinline__ void mma16(float* d, const uint32_t* a, const uint32_t* b) {
    asm volatile(
        "mma.sync.aligned.m16n8k16.row.col.f32.bf16.bf16.f32 "
        "{%0,%1,%2,%3}, {%4,%5,%6,%7}, {%8,%9}, {%0,%1,%2,%3};"
        : "+f"(d[0]), "+f"(d[1]), "+f"(d[2]), "+f"(d[3])
        : "r"(a[0]), "r"(a[1]), "r"(a[2]), "r"(a[3]), "r"(b[0]), "r"(b[1]));
}
__device__ __forceinline__ void ldsm4(uint32_t* r, uint32_t a) {
    asm volatile("ldmatrix.sync.aligned.m8n8.x4.shared.b16 {%0,%1,%2,%3}, [%4];"
        : "=r"(r[0]), "=r"(r[1]), "=r"(r[2]), "=r"(r[3]) : "r"(a));
}
__device__ __forceinline__ void ldsm4t(uint32_t* r, uint32_t a) {
    asm volatile("ldmatrix.sync.aligned.m8n8.x4.trans.shared.b16 {%0,%1,%2,%3}, [%4];"
        : "=r"(r[0]), "=r"(r[1]), "=r"(r[2]), "=r"(r[3]) : "r"(a));
}
__device__ __forceinline__ void cp16(uint32_t saddr, const void* g) {
    asm volatile("cp.async.cg.shared.global [%0], [%1], 16;" :: "r"(saddr), "l"(g));
}
#define CP_COMMIT() asm volatile("cp.async.commit_group;" ::: "memory")
#define CP_WAIT1()  asm volatile("cp.async.wait_group 1;" ::: "memory")
#define CP_WAIT0()  asm volatile("cp.async.wait_group 0;" ::: "memory")
__device__ __forceinline__ uint32_t smem_u32(const void* p) {
    uint32_t a;
    asm("{ .reg .u64 t; cvta.to.shared.u64 t, %1; cvt.u32.u64 %0, t; }" : "=r"(a) : "l"(p));
    return a;
}

// ===========================================================================
// LayerNorm: x (B, C, T) -> hn (B*T, C) bf16, coalesced two-pass tiles
// ===========================================================================
__global__ void ln_kernel(const float* __restrict__ x, const float* __restrict__ gamma,
                          const float* __restrict__ beta, __nv_bfloat16* __restrict__ hn) {
    int b = blockIdx.y, t0 = blockIdx.x * 32;
    int tid = threadIdx.x;
    int tx = tid & 31, cy = tid >> 5;   // 8 c-lanes
    const float* xp = x + (size_t)b * CIN * SEQT + t0;
    float s = 0.f, s2 = 0.f;
#pragma unroll 8
    for (int c = cy; c < CIN; c += 8) {
        float v = xp[(size_t)c * SEQT + tx];
        s += v; s2 += v * v;
    }
    __shared__ float ss[8][32], ss2[8][32], mean_s[32], rstd_s[32];
    ss[cy][tx] = s; ss2[cy][tx] = s2;
    __syncthreads();
    if (cy == 0) {
        float S = 0.f, S2 = 0.f;
#pragma unroll
        for (int i = 0; i < 8; i++) { S += ss[i][tx]; S2 += ss2[i][tx]; }
        float mean = S * (1.f / CIN);
        float var = S2 * (1.f / CIN) - mean * mean;
        mean_s[tx] = mean;
        rstd_s[tx] = rsqrtf(var + 1e-5f);
    }
    __syncthreads();
    float mean = mean_s[tx], rstd = rstd_s[tx];
    __shared__ float tile[32][33];
    for (int c0 = 0; c0 < CIN; c0 += 32) {
#pragma unroll
        for (int j = 0; j < 4; j++) {
            int c = c0 + cy + j * 8;
            tile[cy + j * 8][tx] = (xp[(size_t)c * SEQT + tx] - mean) * rstd * gamma[c] + beta[c];
        }
        __syncthreads();
#pragma unroll
        for (int j = 0; j < 4; j++) {
            int t = cy + j * 8;
            hn[(size_t)(b * SEQT + t0 + t) * CIN + c0 + tx] = __float2bfloat16(tile[tx][t]);
        }
        __syncthreads();
    }
}

// ===========================================================================
// single pack/convert: wq|wk|wv -> wqkv[512][1536] bf16, wo -> bf16,
// bq|bk|bv -> bqkv[1536] fp32
// ===========================================================================
__global__ void cvt_pack(const float* __restrict__ wq, const float* __restrict__ wk,
                         const float* __restrict__ wv, const float* __restrict__ wo,
                         const float* __restrict__ bq, const float* __restrict__ bk,
                         const float* __restrict__ bv,
                         __nv_bfloat16* __restrict__ wqkv, __nv_bfloat16* __restrict__ wob,
                         float* __restrict__ bqkv) {
    int t = blockIdx.x * 256 + threadIdx.x;
    int i = t * 4;                       // over 4*512*512 = 1M floats
    int w = i >> 18;                     // which weight
    int r = i & 0x3FFFF;
    const float* src = (w == 0) ? wq : (w == 1) ? wk : (w == 2) ? wv : wo;
    float4 v = *(const float4*)(src + r);
    uint2 p = {pk(v.x, v.y), pk(v.z, v.w)};
    if (w < 3) {
        int kk = r >> 9, n = r & 511;
        *(uint2*)(wqkv + (size_t)kk * 1536 + w * 512 + n) = p;
    } else {
        *(uint2*)(wob + r) = p;
    }
    if (t < 3 * DF)
        bqkv[t] = (t < 512) ? bq[t] : (t < 1024) ? bk[t - 512] : bv[t - 1024];
}

// ===========================================================================
// fused QKV GEMM: qkv[M,1536] = hn[M,512] @ wqkv[512,1536] + bqkv
// q-columns (bn<512) scaled by log2e/8. 128x128 tile, BK=64, 256 thr.
// ===========================================================================
#define GA_SZ 16384
#define GB_SZ 16384
#define GBUF  (GA_SZ + GB_SZ)
#define GEMM_SMEM (2 * GBUF)   // 65536

__global__ __launch_bounds__(256, 2)
void gemm_qkv(const __nv_bfloat16* __restrict__ A, const __nv_bfloat16* __restrict__ W,
              const float* __restrict__ bias, __nv_bfloat16* __restrict__ C) {
    extern __shared__ char sm[];
    uint32_t sb = smem_u32(sm);
    const int tid = threadIdx.x;
    const int wid = tid >> 5, lane = tid & 31;
    const int g = lane >> 2, tg = lane & 3;
    const int bm = blockIdx.y * 128, bn = blockIdx.x * 128;
    const int wm = (wid & 3) * 32, wn = (wid >> 2) * 64;
    const float scale = (bn < 512) ? 0.125f * 1.44269504088896f : 1.0f;

#define G_ISSUE(kt, buf) do {                                                        \
        uint32_t base_ = sb + (uint32_t)(buf) * GBUF;                                \
        _Pragma("unroll")                                                            \
        for (int i_ = 0; i_ < 4; i_++) {                                             \
            int idx = tid + i_ * 256;                                                \
            int r = idx >> 3, c = idx & 7;                                           \
            cp16(base_ + r * 128 + ((c ^ (r & 7)) << 4),                             \
                 A + (size_t)(bm + r) * 512 + (kt) * 64 + c * 8);                    \
        }                                                                            \
        _Pragma("unroll")                                                            \
        for (int i_ = 0; i_ < 4; i_++) {                                             \
            int idx = tid + i_ * 256;                                                \
            int r = idx >> 4, c = idx & 15;                                          \
            cp16(base_ + GA_SZ + r * 256 + ((c ^ (r & 7)) << 4),                     \
                 W + (size_t)((kt) * 64 + r) * 1536 + bn + c * 8);                   \
        }                                                                            \
        CP_COMMIT();                                                                 \
    } while (0)

    float acc[2][8][4];
#pragma unroll
    for (int mt = 0; mt < 2; mt++)
#pragma unroll
        for (int nt = 0; nt < 8; nt++)
#pragma unroll
            for (int j = 0; j < 4; j++) acc[mt][nt][j] = 0.f;

    G_ISSUE(0, 0);
    for (int kt = 0; kt < 8; kt++) {
        if (kt < 7) { G_ISSUE(kt + 1, (kt + 1) & 1); CP_WAIT1(); }
        else CP_WAIT0();
        __syncthreads();
        uint32_t base = sb + (kt & 1) * GBUF;
#pragma unroll
        for (int ks = 0; ks < 4; ks++) {
            uint32_t a[2][4];
#pragma unroll
            for (int mt = 0; mt < 2; mt++) {
                int row = wm + mt * 16 + (lane & 7) + ((lane & 8) ? 8 : 0);
                int c = ks * 2 + ((lane >> 4) & 1);
                ldsm4(a[mt], base + row * 128 + ((c ^ (row & 7)) << 4));
            }
            uint32_t bb[4][4];
#pragma unroll
            for (int j = 0; j < 4; j++) {
                int krow = ks * 16 + (lane & 7) + ((lane & 8) ? 8 : 0);
                int c = ((wn + j * 16) >> 3) + ((lane >> 4) & 1);
                ldsm4t(bb[j], base + GA_SZ + krow * 256 + ((c ^ (krow & 7)) << 4));
            }
#pragma unroll
            for (int mt = 0; mt < 2; mt++)
#pragma unroll
                for (int j = 0; j < 4; j++) {
                    mma16(acc[mt][2 * j], a[mt], &bb[j][0]);
                    mma16(acc[mt][2 * j + 1], a[mt], &bb[j][2]);
                }
        }
        __syncthreads();
    }

#pragma unroll
    for (int mt = 0; mt < 2; mt++) {
        int row = bm + wm + mt * 16 + g;
#pragma unroll
        for (int nt = 0; nt < 8; nt++) {
            int col = bn + wn + nt * 8 + 2 * tg;
            float b0 = bias[col], b1 = bias[col + 1];
            uint32_t* Cw = (uint32_t*)C;
            Cw[((size_t)row * 1536 + col) >> 1] =
                pk((acc[mt][nt][0] + b0) * scale, (acc[mt][nt][1] + b1) * scale);
            Cw[((size_t)(row + 8) * 1536 + col) >> 1] =
                pk((acc[mt][nt][2] + b0) * scale, (acc[mt][nt][3] + b1) * scale);
        }
    }
#undef G_ISSUE
}

// ===========================================================================
// output GEMM + residual + transpose: out[b][c][t] = x[b][c][t] +
//   (ctx[b*T+t][:] @ wo)[c] + bo[c]
// ===========================================================================
__global__ __launch_bounds__(256, 2)
void gemm_out(const __nv_bfloat16* __restrict__ A, const __nv_bfloat16* __restrict__ W,
              const float* __restrict__ bias, const float* __restrict__ x,
              float* __restrict__ out) {
    extern __shared__ char sm[];
    uint32_t sb = smem_u32(sm);
    const int tid = threadIdx.x;
    const int wid = tid >> 5, lane = tid & 31;
    const int g = lane >> 2, tg = lane & 3;
    const int bm = blockIdx.y * 128, bn = blockIdx.x * 128;
    const int wm = (wid & 3) * 32, wn = (wid >> 2) * 64;

#define G_ISSUE(kt, buf) do {                                                        \
        uint32_t base_ = sb + (uint32_t)(buf) * GBUF;                                \
        _Pragma("unroll")                                                            \
        for (int i_ = 0; i_ < 4; i_++) {                                             \
            int idx = tid + i_ * 256;                                                \
            int r = idx >> 3, c = idx & 7;                                           \
            cp16(base_ + r * 128 + ((c ^ (r & 7)) << 4),                             \
                 A + (size_t)(bm + r) * 512 + (kt) * 64 + c * 8);                    \
        }                                                                            \
        _Pragma("unroll")                                                            \
        for (int i_ = 0; i_ < 4; i_++) {                                             \
            int idx = tid + i_ * 256;                                                \
            int r = idx >> 4, c = idx & 15;                                          \
            cp16(base_ + GA_SZ + r * 256 + ((c ^ (r & 7)) << 4),                     \
                 W + (size_t)((kt) * 64 + r) * 512 + bn + c * 8);                    \
        }                                                                            \
        CP_COMMIT();                                                                 \
    } while (0)

    float acc[2][8][4];
#pragma unroll
    for (int mt = 0; mt < 2; mt++)
#pragma unroll
        for (int nt = 0; nt < 8; nt++)
#pragma unroll
            for (int j = 0; j < 4; j++) acc[mt][nt][j] = 0.f;

    G_ISSUE(0, 0);
    for (int kt = 0; kt < 8; kt++) {
        if (kt < 7) { G_ISSUE(kt + 1, (kt + 1) & 1); CP_WAIT1(); }
        else CP_WAIT0();
        __syncthreads();
        uint32_t base = sb + (kt & 1) * GBUF;
#pragma unroll
        for (int ks = 0; ks < 4; ks++) {
            uint32_t a[2][4];
#pragma unroll
            for (int mt = 0; mt < 2; mt++) {
                int row = wm + mt * 16 + (lane & 7) + ((lane & 8) ? 8 : 0);
                int c = ks * 2 + ((lane >> 4) & 1);
                ldsm4(a[mt], base + row * 128 + ((c ^ (row & 7)) << 4));
            }
            uint32_t bb[4][4];
#pragma unroll
            for (int j = 0; j < 4; j++) {
                int krow = ks * 16 + (lane & 7) + ((lane & 8) ? 8 : 0);
                int c = ((wn + j * 16) >> 3) + ((lane >> 4) & 1);
                ldsm4t(bb[j], base + GA_SZ + krow * 256 + ((c ^ (krow & 7)) << 4));
            }
#pragma unroll
            for (int mt = 0; mt < 2; mt++)
#pragma unroll
                for (int j = 0; j < 4; j++) {
                    mma16(acc[mt][2 * j], a[mt], &bb[j][0]);
                    mma16(acc[mt][2 * j + 1], a[mt], &bb[j][2]);
                }
        }
        __syncthreads();
    }

    // epilogue: transpose + residual. row=(b,t), col=c -> out[((b*512+c)*2048)+t]
#pragma unroll
    for (int mt = 0; mt < 2; mt++) {
        int row = bm + wm + mt * 16 + g;
        int bI = row >> 11, t = row & 2047;
#pragma unroll
        for (int nt = 0; nt < 8; nt++) {
            int col = bn + wn + nt * 8 + 2 * tg;
            float b0 = bias[col], b1 = bias[col + 1];
            size_t i00 = ((size_t)(bI * 512 + col)) * 2048 + t;
            size_t i10 = i00 + 2048;             // col+1
            out[i00]     = x[i00]     + acc[mt][nt][0] + b0;
            out[i10]     = x[i10]     + acc[mt][nt][1] + b1;
            out[i00 + 8] = x[i00 + 8] + acc[mt][nt][2] + b0;   // row+8 -> t+8
            out[i10 + 8] = x[i10 + 8] + acc[mt][nt][3] + b1;
        }
    }
#undef G_ISSUE
}

// ===========================================================================
// Flash attention, causal, bf16 mma, qkv packed (row stride 1536).
// CTA = 128 q rows, 8 warps x 16 rows, reversed qt order (long tiles first).
// ===========================================================================
#define FQ_SZ 16384
#define FKV_SZ 16384
#define FLASH_SMEM (FQ_SZ + 2 * FKV_SZ)   // 49152
#define QKV_ST 1536

__global__ __launch_bounds__(256, 2)
void flash_bf16(const __nv_bfloat16* __restrict__ qkv, __nv_bfloat16* __restrict__ ctx) {
    extern __shared__ char sm[];
    uint32_t sb = smem_u32(sm);
    const int qt = (int)(gridDim.x - 1 - blockIdx.x);   // heavy tiles first
    const int bh = blockIdx.y;
    const int b = bh >> 3, h = bh & 7;
    const int qb = qt * 128;
    const int tid = threadIdx.x, wid = tid >> 5, lane = tid & 31;
    const int g = lane >> 2, tg = lane & 3;
    const int rowbase = qb + wid * 16;
    const int ktmax = 2 * qt + 2;

    const __nv_bfloat16* qp  = qkv + (size_t)(b * SEQT + qb) * QKV_ST + h * 64;
    const __nv_bfloat16* kb0 = qkv + (size_t)b * SEQT * QKV_ST + 512 + h * 64;
    const __nv_bfloat16* vb0 = qkv + (size_t)b * SEQT * QKV_ST + 1024 + h * 64;

#define F_ISSUE(kt, buf) do {                                                        \
        uint32_t base_ = sb + FQ_SZ + (uint32_t)(buf) * FKV_SZ;                      \
        const __nv_bfloat16* kp_ = kb0 + (size_t)(kt) * 64 * QKV_ST;                 \
        const __nv_bfloat16* vp_ = vb0 + (size_t)(kt) * 64 * QKV_ST;                 \
        _Pragma("unroll")                                                            \
        for (int i_ = 0; i_ < 2; i_++) {                                             \
            int idx = tid + i_ * 256;                                                \
            int r = idx >> 3, c = idx & 7;                                           \
            uint32_t off = r * 128 + ((c ^ (r & 7)) << 4);                           \
            cp16(base_ + off, kp_ + (size_t)r * QKV_ST + c * 8);                     \
            cp16(base_ + 8192 + off, vp_ + (size_t)r * QKV_ST + c * 8);              \
        }                                                                            \
        CP_COMMIT();                                                                 \
    } while (0)

#pragma unroll
    for (int i = 0; i < 4; i++) {
        int idx = tid + i * 256;
        int r = idx >> 3, c = idx & 7;
        cp16(sb + r * 128 + ((c ^ (r & 7)) << 4), qp + (size_t)r * QKV_ST + c * 8);
    }
    {
        uint32_t base_ = sb + FQ_SZ;
#pragma unroll
        for (int i = 0; i < 2; i++) {
            int idx = tid + i * 256;
            int r = idx >> 3, c = idx & 7;
            uint32_t off = r * 128 + ((c ^ (r & 7)) << 4);
            cp16(base_ + off, kb0 + (size_t)r * QKV_ST + c * 8);
            cp16(base_ + 8192 + off, vb0 + (size_t)r * QKV_ST + c * 8);
        }
        CP_COMMIT();
    }
    if (ktmax > 1) F_ISSUE(1, 1);

    float o[8][4];
#pragma unroll
    for (int nt = 0; nt < 8; nt++)
#pragma unroll
        for (int j = 0; j < 4; j++) o[nt][j] = 0.f;
    float m0 = -1e29f, m1 = -1e29f, l0 = 0.f, l1 = 0.f;
    uint32_t aq[4][4];

    for (int kt = 0; kt < ktmax; kt++) {
        if (kt + 1 < ktmax) CP_WAIT1(); else CP_WAIT0();
        __syncthreads();
        if (kt == 0) {
#pragma unroll
            for (int ks = 0; ks < 4; ks++) {
                int row = wid * 16 + (lane & 7) + ((lane & 8) ? 8 : 0);
                int c = ks * 2 + ((lane >> 4) & 1);
                ldsm4(aq[ks], sb + row * 128 + ((c ^ (row & 7)) << 4));
            }
        }
        if (kt * 64 <= rowbase + 15) {
            uint32_t base = sb + FQ_SZ + (kt & 1) * FKV_SZ;
            float S[8][4];
#pragma unroll
            for (int nt = 0; nt < 8; nt++)
#pragma unroll
                for (int j = 0; j < 4; j++) S[nt][j] = 0.f;

#pragma unroll
            for (int ks = 0; ks < 4; ks++) {
#pragma unroll
                for (int j = 0; j < 4; j++) {
                    uint32_t kbf[4];
                    int krow = j * 16 + (lane & 7) + ((lane & 16) ? 8 : 0);
                    int c = ks * 2 + ((lane >> 3) & 1);
                    ldsm4(kbf, base + krow * 128 + ((c ^ (krow & 7)) << 4));
                    mma16(S[2 * j], aq[ks], &kbf[0]);
                    mma16(S[2 * j + 1], aq[ks], &kbf[2]);
                }
            }

            if (kt * 64 + 63 > rowbase) {
#pragma unroll
                for (int nt = 0; nt < 8; nt++)
#pragma unroll
                    for (int j = 0; j < 4; j++) {
                        int col = kt * 64 + nt * 8 + 2 * tg + (j & 1);
                        int row = rowbase + g + ((j >> 1) << 3);
                        if (col > row) S[nt][j] = -1e30f;
                    }
            }

            float rm0 = -1e30f, rm1 = -1e30f;
#pragma unroll
            for (int nt = 0; nt < 8; nt++) {
                rm0 = fmaxf(rm0, fmaxf(S[nt][0], S[nt][1]));
                rm1 = fmaxf(rm1, fmaxf(S[nt][2], S[nt][3]));
            }
            rm0 = fmaxf(rm0, __shfl_xor_sync(0xffffffffu, rm0, 1));
            rm0 = fmaxf(rm0, __shfl_xor_sync(0xffffffffu, rm0, 2));
            rm1 = fmaxf(rm1, __shfl_xor_sync(0xffffffffu, rm1, 1));
            rm1 = fmaxf(rm1, __shfl_xor_sync(0xffffffffu, rm1, 2));
            float mn0 = fmaxf(m0, rm0), mn1 = fmaxf(m1, rm1);
            float al0 = ex2(m0 - mn0), al1 = ex2(m1 - mn1);
            m0 = mn0; m1 = mn1;
            float rs0 = 0.f, rs1 = 0.f;
#pragma unroll
            for (int nt = 0; nt < 8; nt++) {
                S[nt][0] = ex2(S[nt][0] - mn0); rs0 += S[nt][0];
                S[nt][1] = ex2(S[nt][1] - mn0); rs0 += S[nt][1];
                S[nt][2] = ex2(S[nt][2] - mn1); rs1 += S[nt][2];
                S[nt][3] = ex2(S[nt][3] - mn1); rs1 += S[nt][3];
            }
            rs0 += __shfl_xor_sync(0xffffffffu, rs0, 1);
            rs0 += __shfl_xor_sync(0xffffffffu, rs0, 2);
            rs1 += __shfl_xor_sync(0xffffffffu, rs1, 1);
            rs1 += __shfl_xor_sync(0xffffffffu, rs1, 2);
            l0 = l0 * al0 + rs0;
            l1 = l1 * al1 + rs1;
#pragma unroll
            for (int nt = 0; nt < 8; nt++) {
                o[nt][0] *= al0; o[nt][1] *= al0;
                o[nt][2] *= al1; o[nt][3] *= al1;
            }

#pragma unroll
            for (int ksp = 0; ksp < 4; ksp++) {
                uint32_t ap[4] = {
                    pk(S[2 * ksp][0], S[2 * ksp][1]),
                    pk(S[2 * ksp][2], S[2 * ksp][3]),
                    pk(S[2 * ksp + 1][0], S[2 * ksp + 1][1]),
                    pk(S[2 * ksp + 1][2], S[2 * ksp + 1][3])};
#pragma unroll
                for (int j = 0; j < 4; j++) {
                    uint32_t vbf[4];
                    int krow = ksp * 16 + (lane & 7) + ((lane & 8) ? 8 : 0);
                    int c = j * 2 + ((lane >> 4) & 1);
                    ldsm4t(vbf, base + 8192 + krow * 128 + ((c ^ (krow & 7)) << 4));
                    mma16(o[2 * j], ap, &vbf[0]);
                    mma16(o[2 * j + 1], ap, &vbf[2]);
                }
            }
        }
        __syncthreads();
        if (kt + 2 < ktmax) F_ISSUE(kt + 2, kt & 1);
    }

    float inv0 = 1.f / l0, inv1 = 1.f / l1;
    uint32_t* c0p = (uint32_t*)(ctx + (size_t)(b * SEQT + rowbase + g) * 512 + h * 64);
    uint32_t* c1p = (uint32_t*)(ctx + (size_t)(b * SEQT + rowbase + g + 8) * 512 + h * 64);
#pragma unroll
    for (int nt = 0; nt < 8; nt++) {
        int cw = (nt * 8 + 2 * tg) >> 1;
        c0p[cw] = pk(o[nt][0] * inv0, o[nt][1] * inv0);
        c1p[cw] = pk(o[nt][2] * inv1, o[nt][3] * inv1);
    }
#undef F_ISSUE
}

// ===========================================================================
extern "C" void kernel_launch(void* const* d_in, const int* in_sizes, int n_in,
                              void* d_out, int out_size) {
    const float* x     = (const float*)d_in[0];
    const float* gamma = (const float*)d_in[1];
    const float* beta  = (const float*)d_in[2];
    const float* wq = (const float*)d_in[3];
    const float* bq = (const float*)d_in[4];
    const float* wk = (const float*)d_in[5];
    const float* bk = (const float*)d_in[6];
    const float* wv = (const float*)d_in[7];
    const float* bv = (const float*)d_in[8];
    const float* wo = (const float*)d_in[9];
    const float* bo = (const float*)d_in[10];
    float* out = (float*)d_out;

    __nv_bfloat16 *hn, *qkv, *cb, *wqkv, *wob;
    float *bqkv;
    cudaGetSymbolAddress((void**)&hn,   g_hn);
    cudaGetSymbolAddress((void**)&qkv,  g_qkv);
    cudaGetSymbolAddress((void**)&cb,   g_ctx);
    cudaGetSymbolAddress((void**)&wqkv, g_wqkv);
    cudaGetSymbolAddress((void**)&wob,  g_wo);
    cudaGetSymbolAddress((void**)&bqkv, g_bqkv);

    ln_kernel<<<dim3(SEQT / 32, BATCH), 256>>>(x, gamma, beta, hn);
    cvt_pack<<<1024, 256>>>(wq, wk, wv, wo, bq, bk, bv, wqkv, wob, bqkv);

    cudaFuncSetAttribute(gemm_qkv, cudaFuncAttributeMaxDynamicSharedMemorySize, GEMM_SMEM);
    cudaFuncSetAttribute(gemm_out, cudaFuncAttributeMaxDynamicSharedMemorySize, GEMM_SMEM);
    gemm_qkv<<<dim3(12, MROWS / 128), 256, GEMM_SMEM>>>(hn, wqkv, bqkv, qkv);

    cudaFuncSetAttribute(flash_bf16, cudaFuncAttributeMaxDynamicSharedMemorySize, FLASH_SMEM);
    flash_bf16<<<dim3(SEQT / 128, BATCH * NH), 256, FLASH_SMEM>>>(qkv, cb);

    gemm_out<<<dim3(4, MROWS / 128), 256, GEMM_SMEM>>>(cb, wob, bo, x, out);
}